// round 3
// baseline (speedup 1.0000x reference)
#include <cuda_runtime.h>
#include <math.h>

// Problem constants (fixed by the reference)
#define N_K        16
#define C_CAT      136          // 16*17/2 upper-tri pairs
#define N_DIAG     16
#define N_NONDIAG  120
#define DIM        64
#define NROWS      8192         // 512 * 16
#define ROWS_PER_BLK 4
#define MAIN_BLOCKS (NROWS / ROWS_PER_BLK)   // 2048

#define LOG2PI_F   1.8378770664093453f
#define NEG_RSQRT2 (-0.70710678118654752440f)

// ---- device scratch (static globals; no allocation) ----
__device__ float4 d_c4[C_CAT];   // {k1, mB2, recip, sq}
__device__ float2 d_cb[C_CAT];   // {base, bitcast(A | B<<8)}
__device__ float  d_partials[MAIN_BLOCKS];
__device__ unsigned int d_counter = 0;

// ---------------------------------------------------------------------------
// Kernel 1: per-category constants.  17 blocks x 256 thr; one WARP per category.
// Categories are stored REORDERED: non-diag pairs in slots [0,120), diagonal
// (A==B, inv_sig==0) pairs in slots [120,136).
// ---------------------------------------------------------------------------
__global__ __launch_bounds__(256) void precompute_kernel(const float* __restrict__ pi,
                                                         const float* __restrict__ mu)
{
    __shared__ float red[256];
    __shared__ float s_max, s_sum;
    const int t = threadIdx.x;
    const int w = t >> 5, l = t & 31;

    // block-redundant softmax denom over 136 logits
    const float piv = (t < C_CAT) ? pi[t] : -INFINITY;
    red[t] = piv; __syncthreads();
    for (int o = 128; o; o >>= 1) { if (t < o) red[t] = fmaxf(red[t], red[t + o]); __syncthreads(); }
    if (t == 0) s_max = red[0];
    __syncthreads();
    red[t] = (t < C_CAT) ? __expf(piv - s_max) : 0.f;
    __syncthreads();
    for (int o = 128; o; o >>= 1) { if (t < o) red[t] += red[t + o]; __syncthreads(); }
    if (t == 0) s_sum = red[0];
    __syncthreads();

    const int c = blockIdx.x * 8 + w;          // natural category index
    if (c >= C_CAT) return;

    // decode (A,B) from natural upper-tri row-major index
    int A = 0, rem = c;
    while (rem >= (N_K - A)) { rem -= (N_K - A); ++A; }
    const int B = A + rem;

    // warp-parallel 64-dim dots: lane handles dims l and l+32
    float invsig = 0.f, k1 = 0.f, mB2 = 0.f;
    #pragma unroll
    for (int h = 0; h < 2; ++h) {
        const int d = l + h * 32;
        const float mb = mu[d * N_K + B];
        const float ma = mu[d * N_K + A];
        const float a  = mb - ma;
        invsig = fmaf(a, a, invsig);
        k1     = fmaf(a, mb, k1);
        mB2    = fmaf(mb, mb, mB2);
    }
    #pragma unroll
    for (int o = 16; o; o >>= 1) {
        invsig += __shfl_xor_sync(0xffffffffu, invsig, o);
        k1     += __shfl_xor_sync(0xffffffffu, k1, o);
        mB2    += __shfl_xor_sync(0xffffffffu, mB2, o);
    }

    if (l == 0) {
        const float e  = __expf(pi[c] - s_max);
        const float tp = fminf(fmaxf(e / s_sum, 1e-16f), 1.0f);
        const float lp = -32.0f * LOG2PI_F + logf(tp);

        const int diag = (A == B);
        const int slot = diag ? (N_NONDIAG + A) : (c - A - 1);

        float base, recip, sq;
        if (diag) {
            base = lp; recip = 0.f; sq = 0.f;
        } else {
            const float clip_is = fminf(fmaxf(invsig, 1e-12f), 1e30f);
            sq    = sqrtf(clip_is);
            base  = lp + 0.5f * (LOG2PI_F - logf(clip_is));
            recip = 1.0f / invsig;
        }
        d_c4[slot] = make_float4(k1, mB2, recip, sq);
        d_cb[slot] = make_float2(base, __int_as_float(A | (B << 8)));
    }
}

// ---------------------------------------------------------------------------
// Kernel 2: main. 4 rows/block, one warp per row; fused last-block finalize.
// ---------------------------------------------------------------------------
__global__ __launch_bounds__(128) void main_kernel(const float* __restrict__ z,
                                                   const float* __restrict__ mu,
                                                   float* __restrict__ out)
{
    __shared__ float  mu_s[DIM][N_K];               // 4 KB
    __shared__ float  z_s [ROWS_PER_BLK][DIM];      // 1 KB
    __shared__ float  g_s [ROWS_PER_BLK][N_K];
    __shared__ float4 c4_s[C_CAT];                  // 2176 B
    __shared__ float2 cb_s[C_CAT];                  // 1088 B
    __shared__ float  rowres[ROWS_PER_BLK];
    __shared__ float  red[128];
    __shared__ int    s_is_last;

    const int t = threadIdx.x;

    // ---- stage everything ----
    for (int i = t; i < DIM * N_K; i += 128)
        (&mu_s[0][0])[i] = mu[i];
    const int row0 = blockIdx.x * ROWS_PER_BLK;
    for (int i = t; i < ROWS_PER_BLK * DIM; i += 128)
        (&z_s[0][0])[i] = z[row0 * DIM + i];
    for (int i = t; i < C_CAT; i += 128) {
        c4_s[i] = d_c4[i];
        cb_s[i] = d_cb[i];
    }
    __syncthreads();

    const int w = t >> 5;        // warp == row within block
    const int l = t & 31;

    // |z|^2
    float p = z_s[w][l] * z_s[w][l] + z_s[w][l + 32] * z_s[w][l + 32];
    #pragma unroll
    for (int o = 16; o; o >>= 1) p += __shfl_xor_sync(0xffffffffu, p, o);
    const float z2 = p;

    // g_k = dot(z_row, mu_k): lane (k,h) does a 32-long partial, fold halves
    {
        const int k = l & 15, h = l >> 4;
        float acc = 0.f;
        #pragma unroll
        for (int d = 0; d < 32; ++d)
            acc = fmaf(z_s[w][h * 32 + d], mu_s[h * 32 + d][k], acc);
        acc += __shfl_xor_sync(0xffffffffu, acc, 16);
        if (h == 0) g_s[w][k] = acc;
    }
    __syncwarp();

    // ---- per-category values, two-pass register-buffered logsumexp ----
    float vbuf[5];
    int nv = 0;
    float m = -INFINITY;

    // non-diagonal slots [0,120): uniform heavy path, no divergence on the
    // first 3 iterations for every lane
    for (int c = l; c < N_NONDIAG; c += 32) {
        const float4 q  = c4_s[c];                  // k1, mB2, recip, sq
        const float2 b2 = cb_s[c];
        const int ab = __float_as_int(b2.y);
        const float gA = g_s[w][ab & 255];
        const float gB = g_s[w][(ab >> 8) & 255];
        const float beta_sq = z2 - 2.0f * gB + q.y;
        const float delta = q.x - gB + gA;
        const float nu = delta * q.z;
        const float tq = fmaf(delta, nu, -beta_sq);  // nu^2*invsig - beta_sq
        const float eta1 = (1.0f - nu) * q.w;
        const float eta2 = -nu * q.w;
        float cdfd = 0.5f * (erfcf(eta1 * NEG_RSQRT2) - erfcf(eta2 * NEG_RSQRT2));
        cdfd = fminf(fmaxf(cdfd, 1e-16f), 1e30f);
        const float v = b2.x + 0.5f * tq + __logf(cdfd);
        vbuf[nv++] = v;
        m = fmaxf(m, v);
    }
    // diagonal slots [120,136): cheap path, lanes 0..15 only
    if (l < N_DIAG) {
        const int c = N_NONDIAG + l;
        const float4 q  = c4_s[c];
        const float2 b2 = cb_s[c];
        const int ab = __float_as_int(b2.y);
        const float gB = g_s[w][(ab >> 8) & 255];
        const float beta_sq = z2 - 2.0f * gB + q.y;
        const float v = b2.x - 0.5f * beta_sq;
        vbuf[nv++] = v;
        m = fmaxf(m, v);
    }

    // warp max
    #pragma unroll
    for (int o = 16; o; o >>= 1) m = fmaxf(m, __shfl_xor_sync(0xffffffffu, m, o));

    float ssum = 0.f;
    #pragma unroll
    for (int i = 0; i < 5; ++i)
        if (i < nv) ssum += __expf(vbuf[i] - m);

    #pragma unroll
    for (int o = 16; o; o >>= 1) ssum += __shfl_xor_sync(0xffffffffu, ssum, o);

    if (l == 0) rowres[w] = m + logf(ssum);
    __syncthreads();

    // ---- per-block partial + last-block-done finalize ----
    if (t == 0) {
        float s = 0.f;
        #pragma unroll
        for (int r = 0; r < ROWS_PER_BLK; ++r) s += rowres[r];
        d_partials[blockIdx.x] = s;
        __threadfence();
        const unsigned int ticket = atomicAdd(&d_counter, 1u);
        s_is_last = (ticket == (unsigned)(gridDim.x - 1));
    }
    __syncthreads();

    if (s_is_last) {
        volatile float* vp = d_partials;
        float s = 0.f;
        for (int i = t; i < MAIN_BLOCKS; i += 128) s += vp[i];
        red[t] = s; __syncthreads();
        for (int o = 64; o; o >>= 1) { if (t < o) red[t] += red[t + o]; __syncthreads(); }
        if (t == 0) {
            out[0] = red[0] * (1.0f / (float)NROWS);
            d_counter = 0;                 // reset for next graph replay
        }
    }
}

// ---------------------------------------------------------------------------
extern "C" void kernel_launch(void* const* d_in, const int* in_sizes, int n_in,
                              void* d_out, int out_size)
{
    (void)in_sizes; (void)n_in; (void)out_size;
    const float* z  = (const float*)d_in[0];
    const float* pi = (const float*)d_in[1];
    const float* mu = (const float*)d_in[2];
    float* out = (float*)d_out;

    precompute_kernel<<<17, 256>>>(pi, mu);
    main_kernel<<<MAIN_BLOCKS, 128>>>(z, mu, out);
}

// round 4
// speedup vs baseline: 1.1449x; 1.1449x over previous
#include <cuda_runtime.h>
#include <math.h>

// Problem constants (fixed by the reference)
#define N_K        16
#define C_CAT      136          // 16*17/2 upper-tri pairs
#define C_PAD      160          // padded to 32*5 for a uniform unrolled loop
#define DIM        64
#define NROWS      8192         // 512 * 16
#define ROWS_PER_BLK 8
#define MAIN_BLOCKS (NROWS / ROWS_PER_BLK)   // 1024

#define LOG2PI_F   1.8378770664093453f
#define LN2_F      0.6931471805599453f
#define NEG_RSQRT2 (-0.70710678118654752440f)

// ---- device scratch (static globals; no allocation) ----
__device__ float4 d_c4[C_PAD];   // {k1, half_mB2, recip, sq}
__device__ float2 d_cb[C_PAD];   // {base, bitcast(A | B<<8)}
__device__ float  d_partials[MAIN_BLOCKS];
__device__ unsigned int d_counter = 0;

// ---------------------------------------------------------------------------
// Kernel 1: per-category constants. 17 blocks x 256 thr; one WARP per category.
// Diagonal pairs (A==B, inv_sig==0) are ENCODED as heavy-path categories:
//   k1=0, recip=0, sq=40, base=lp+ln2  ->  nu=0, tq=-beta_sq,
//   cdfd = 0.5*(erfcf(-28.3)-erfcf(0)) = 0.5,  v = lp - 0.5*beta_sq  (exact).
// Slots [136,160) are -inf-like padding.
// ---------------------------------------------------------------------------
__global__ __launch_bounds__(256) void precompute_kernel(const float* __restrict__ pi,
                                                         const float* __restrict__ mu)
{
    __shared__ float red[256];
    __shared__ float s_max, s_sum;
    const int t = threadIdx.x;
    const int w = t >> 5, l = t & 31;

    // block-redundant softmax denominator over the 136 logits
    const float piv = (t < C_CAT) ? pi[t] : -INFINITY;
    red[t] = piv; __syncthreads();
    for (int o = 128; o; o >>= 1) { if (t < o) red[t] = fmaxf(red[t], red[t + o]); __syncthreads(); }
    if (t == 0) s_max = red[0];
    __syncthreads();
    red[t] = (t < C_CAT) ? __expf(piv - s_max) : 0.f;
    __syncthreads();
    for (int o = 128; o; o >>= 1) { if (t < o) red[t] += red[t + o]; __syncthreads(); }
    if (t == 0) s_sum = red[0];
    __syncthreads();

    // padding slots (block 0, threads 136..159 of the flat index space)
    if (blockIdx.x == 0 && t >= C_CAT && t < C_PAD) {
        d_c4[t] = make_float4(0.f, 0.f, 0.f, 40.f);
        d_cb[t] = make_float2(-1e30f, __int_as_float(0));
    }

    const int c = blockIdx.x * 8 + w;          // category index
    if (c >= C_CAT) return;

    // decode (A,B) from upper-tri row-major index
    int A = 0, rem = c;
    while (rem >= (N_K - A)) { rem -= (N_K - A); ++A; }
    const int B = A + rem;

    // warp-parallel 64-dim dots: lane handles dims l and l+32
    float invsig = 0.f, k1 = 0.f, mB2 = 0.f;
    #pragma unroll
    for (int h = 0; h < 2; ++h) {
        const int d = l + h * 32;
        const float mb = mu[d * N_K + B];
        const float ma = mu[d * N_K + A];
        const float a  = mb - ma;
        invsig = fmaf(a, a, invsig);
        k1     = fmaf(a, mb, k1);
        mB2    = fmaf(mb, mb, mB2);
    }
    #pragma unroll
    for (int o = 16; o; o >>= 1) {
        invsig += __shfl_xor_sync(0xffffffffu, invsig, o);
        k1     += __shfl_xor_sync(0xffffffffu, k1, o);
        mB2    += __shfl_xor_sync(0xffffffffu, mB2, o);
    }

    if (l == 0) {
        const float e  = __expf(pi[c] - s_max);
        const float tp = fminf(fmaxf(e / s_sum, 1e-16f), 1.0f);
        const float lp = -32.0f * LOG2PI_F + logf(tp);

        float base, recip, sq, k1s;
        if (A == B) {                       // diag: inv_sig == 0
            base = lp + LN2_F; recip = 0.f; sq = 40.f; k1s = 0.f;
        } else {
            const float clip_is = fminf(fmaxf(invsig, 1e-12f), 1e30f);
            sq    = sqrtf(clip_is);
            base  = lp + 0.5f * (LOG2PI_F - logf(clip_is));
            recip = 1.0f / invsig;
            k1s   = k1;
        }
        d_c4[c] = make_float4(k1s, 0.5f * mB2, recip, sq);
        d_cb[c] = make_float2(base, __int_as_float(A | (B << 8)));
    }
}

// ---------------------------------------------------------------------------
// Kernel 2: main. 8 rows/block (256 thr), one warp per row.
// Uniform branchless hot loop: exactly 5 categories per lane, full unroll.
// Fused last-block-done finalize.
// ---------------------------------------------------------------------------
__global__ __launch_bounds__(256) void main_kernel(const float* __restrict__ z,
                                                   const float* __restrict__ mu,
                                                   float* __restrict__ out)
{
    __shared__ float  mu_s[DIM][N_K];               // 4 KB
    __shared__ float  z_s [ROWS_PER_BLK][DIM];      // 2 KB
    __shared__ float  g_s [ROWS_PER_BLK][N_K];      // 512 B
    __shared__ float4 c4_s[C_PAD];                  // 2560 B
    __shared__ float2 cb_s[C_PAD];                  // 1280 B
    __shared__ float  rowres[ROWS_PER_BLK];
    __shared__ float  red[256];
    __shared__ int    s_is_last;

    const int t = threadIdx.x;

    // ---- stage everything ----
    for (int i = t; i < DIM * N_K; i += 256)
        (&mu_s[0][0])[i] = mu[i];
    const int row0 = blockIdx.x * ROWS_PER_BLK;
    for (int i = t; i < ROWS_PER_BLK * DIM; i += 256)
        (&z_s[0][0])[i] = z[row0 * DIM + i];
    for (int i = t; i < C_PAD; i += 256) {
        c4_s[i] = d_c4[i];
        cb_s[i] = d_cb[i];
    }
    __syncthreads();

    const int w = t >> 5;        // warp == row within block
    const int l = t & 31;

    // |z|^2 (we use half of it)
    float p = z_s[w][l] * z_s[w][l] + z_s[w][l + 32] * z_s[w][l + 32];
    #pragma unroll
    for (int o = 16; o; o >>= 1) p += __shfl_xor_sync(0xffffffffu, p, o);
    const float z2h = 0.5f * p;

    // g_k = dot(z_row, mu_k): lane (k,h) does a 32-long partial, fold halves
    {
        const int k = l & 15, h = l >> 4;
        float acc = 0.f;
        #pragma unroll
        for (int d = 0; d < 32; ++d)
            acc = fmaf(z_s[w][h * 32 + d], mu_s[h * 32 + d][k], acc);
        acc += __shfl_xor_sync(0xffffffffu, acc, 16);
        if (h == 0) g_s[w][k] = acc;
    }
    __syncwarp();

    // ---- uniform hot loop: 5 categories per lane, fully unrolled ----
    float vbuf[5];
    float m = -INFINITY;
    #pragma unroll
    for (int i = 0; i < 5; ++i) {
        const int c = l + 32 * i;
        const float4 q  = c4_s[c];                  // k1, 0.5*mB2, recip, sq
        const float2 b2 = cb_s[c];
        const int ab = __float_as_int(b2.y);
        const float gA = g_s[w][ab & 255];
        const float gB = g_s[w][(ab >> 8) & 255];
        const float hbsq = z2h - gB + q.y;          // 0.5 * beta_sq
        const float delta = q.x - gB + gA;
        const float nu = delta * q.z;
        const float eta1 = (1.0f - nu) * q.w;
        const float eta2 = -nu * q.w;
        float cdfd = 0.5f * (erfcf(eta1 * NEG_RSQRT2) - erfcf(eta2 * NEG_RSQRT2));
        cdfd = fminf(fmaxf(cdfd, 1e-16f), 1e30f);
        // v = base + 0.5*(delta*nu) - 0.5*beta_sq + log(cdfd)
        const float v = b2.x + fmaf(0.5f * delta, nu, -hbsq) + __logf(cdfd);
        vbuf[i] = v;
        m = fmaxf(m, v);
    }

    // warp max
    #pragma unroll
    for (int o = 16; o; o >>= 1) m = fmaxf(m, __shfl_xor_sync(0xffffffffu, m, o));

    // single exp per category
    float ssum = 0.f;
    #pragma unroll
    for (int i = 0; i < 5; ++i) ssum += __expf(vbuf[i] - m);

    // warp sum
    #pragma unroll
    for (int o = 16; o; o >>= 1) ssum += __shfl_xor_sync(0xffffffffu, ssum, o);

    if (l == 0) rowres[w] = m + logf(ssum);
    __syncthreads();

    // ---- per-block partial + last-block-done finalize ----
    if (t == 0) {
        float s = 0.f;
        #pragma unroll
        for (int r = 0; r < ROWS_PER_BLK; ++r) s += rowres[r];
        d_partials[blockIdx.x] = s;
        __threadfence();
        const unsigned int ticket = atomicAdd(&d_counter, 1u);
        s_is_last = (ticket == (unsigned)(gridDim.x - 1));
    }
    __syncthreads();

    if (s_is_last) {
        volatile float* vp = d_partials;
        float s = 0.f;
        for (int i = t; i < MAIN_BLOCKS; i += 256) s += vp[i];
        red[t] = s; __syncthreads();
        for (int o = 128; o; o >>= 1) { if (t < o) red[t] += red[t + o]; __syncthreads(); }
        if (t == 0) {
            out[0] = red[0] * (1.0f / (float)NROWS);
            d_counter = 0;                 // reset for next graph replay
        }
    }
}

// ---------------------------------------------------------------------------
extern "C" void kernel_launch(void* const* d_in, const int* in_sizes, int n_in,
                              void* d_out, int out_size)
{
    (void)in_sizes; (void)n_in; (void)out_size;
    const float* z  = (const float*)d_in[0];
    const float* pi = (const float*)d_in[1];
    const float* mu = (const float*)d_in[2];
    float* out = (float*)d_out;

    precompute_kernel<<<17, 256>>>(pi, mu);
    main_kernel<<<MAIN_BLOCKS, 256>>>(z, mu, out);
}

// round 5
// speedup vs baseline: 1.3617x; 1.1894x over previous
#include <cuda_runtime.h>
#include <math.h>

// Problem constants (fixed by the reference)
#define N_K        16
#define C_CAT      136          // 16*17/2 upper-tri pairs
#define C_PAD      160          // padded to 32*5 for a uniform unrolled loop
#define DIM        64
#define NROWS      8192         // 512 * 16
#define ROWS_PER_BLK 8
#define MAIN_BLOCKS (NROWS / ROWS_PER_BLK)   // 1024

#define LOG2PI_F   1.8378770664093453f
#define LN2_F      0.6931471805599453f
#define RSQRT2_F   0.70710678118654752440f
#define NEG_L2E_F  (-1.4426950408889634f)

// A&S 7.1.26 erf coefficients (abs err <= 1.5e-7)
#define ERF_P  0.3275911f
#define ERF_A1 0.254829592f
#define ERF_A2 (-0.284496736f)
#define ERF_A3 1.421413741f
#define ERF_A4 (-1.453152027f)
#define ERF_A5 1.061405429f

// ---- device scratch (static globals; no allocation) ----
__device__ float4 d_c4[C_PAD];   // {k1, 0.5*mB2, recip, s2=s/sqrt2}
__device__ float2 d_cb[C_PAD];   // {base, bitcast(A | B<<8)}
__device__ float  d_partials[MAIN_BLOCKS];
__device__ unsigned int d_counter = 0;

__device__ __forceinline__ float rcp_approx(float x) {
    float r; asm("rcp.approx.f32 %0, %1;" : "=f"(r) : "f"(x)); return r;
}
__device__ __forceinline__ float ex2_approx(float x) {
    float r; asm("ex2.approx.f32 %0, %1;" : "=f"(r) : "f"(x)); return r;
}
// branchless erf, abs err <= ~1.5e-7 (A&S 7.1.26)
__device__ __forceinline__ float erf_fast(float x) {
    const float a = fabsf(x);
    const float t = rcp_approx(fmaf(ERF_P, a, 1.0f));
    float p = fmaf(ERF_A5, t, ERF_A4);
    p = fmaf(p, t, ERF_A3);
    p = fmaf(p, t, ERF_A2);
    p = fmaf(p, t, ERF_A1);
    const float e = ex2_approx(a * a * NEG_L2E_F);   // exp(-a^2)
    const float R = p * t * e;
    return copysignf(1.0f - R, x);
}

// ---------------------------------------------------------------------------
// Kernel 1: per-category constants. 17 blocks x 256 thr; one WARP per category.
// Warp-local softmax (no block reductions). Diagonal pairs encoded as heavy
// categories (k1=0, recip=0 -> nu=0, s2=20 -> erf(x1)=1, erf(x2)=0, D=1) with
// base = lp; non-diag base = lp + 0.5*(log2pi - log(clip)) - ln2 (the -ln2
// folds the 0.5 factor of the cdf difference).  Slots [136,160) are padding.
// ---------------------------------------------------------------------------
__global__ __launch_bounds__(256) void precompute_kernel(const float* __restrict__ pi,
                                                         const float* __restrict__ mu)
{
    const int t = threadIdx.x;
    const int w = t >> 5, l = t & 31;

    // padding slots (written by block 0's threads 136..159, harmless dup work)
    if (blockIdx.x == 0 && t >= C_CAT && t < C_PAD) {
        d_c4[t] = make_float4(0.f, 0.f, 0.f, 20.f);
        d_cb[t] = make_float2(-1e30f, __int_as_float(0));
    }

    // warp-local softmax denominator over the 136 logits
    float v0 = pi[l], v1 = pi[l + 32], v2 = pi[l + 64], v3 = pi[l + 96];
    float v4 = (l < 8) ? pi[128 + l] : -INFINITY;
    float mx = fmaxf(fmaxf(fmaxf(v0, v1), fmaxf(v2, v3)), v4);
    #pragma unroll
    for (int o = 16; o; o >>= 1) mx = fmaxf(mx, __shfl_xor_sync(0xffffffffu, mx, o));
    float sm = __expf(v0 - mx) + __expf(v1 - mx) + __expf(v2 - mx) + __expf(v3 - mx)
             + ((l < 8) ? __expf(v4 - mx) : 0.f);
    #pragma unroll
    for (int o = 16; o; o >>= 1) sm += __shfl_xor_sync(0xffffffffu, sm, o);

    const int c = blockIdx.x * 8 + w;          // category index (< 136 always)

    // decode (A,B) from upper-tri row-major index
    int A = 0, rem = c;
    while (rem >= (N_K - A)) { rem -= (N_K - A); ++A; }
    const int B = A + rem;

    // warp-parallel 64-dim dots: lane handles dims l and l+32
    float invsig = 0.f, k1 = 0.f, mB2 = 0.f;
    #pragma unroll
    for (int h = 0; h < 2; ++h) {
        const int d = l + h * 32;
        const float mb = mu[d * N_K + B];
        const float ma = mu[d * N_K + A];
        const float a  = mb - ma;
        invsig = fmaf(a, a, invsig);
        k1     = fmaf(a, mb, k1);
        mB2    = fmaf(mb, mb, mB2);
    }
    #pragma unroll
    for (int o = 16; o; o >>= 1) {
        invsig += __shfl_xor_sync(0xffffffffu, invsig, o);
        k1     += __shfl_xor_sync(0xffffffffu, k1, o);
        mB2    += __shfl_xor_sync(0xffffffffu, mB2, o);
    }

    if (l == 0) {
        const float e  = __expf(pi[c] - mx);
        const float tp = fminf(fmaxf(e / sm, 1e-16f), 1.0f);
        const float lp = -32.0f * LOG2PI_F + logf(tp);

        float base, recip, s2, k1s;
        if (A == B) {                       // diag: inv_sig == 0
            base = lp; recip = 0.f; s2 = 20.f; k1s = 0.f;
        } else {
            const float clip_is = fminf(fmaxf(invsig, 1e-12f), 1e30f);
            s2    = sqrtf(clip_is) * RSQRT2_F;
            base  = lp + 0.5f * (LOG2PI_F - logf(clip_is)) - LN2_F;
            recip = 1.0f / invsig;
            k1s   = k1;
        }
        d_c4[c] = make_float4(k1s, 0.5f * mB2, recip, s2);
        d_cb[c] = make_float2(base, __int_as_float(A | (B << 8)));
    }
}

// ---------------------------------------------------------------------------
// Kernel 2: main. 8 rows/block (256 thr), one warp per row.
// Exp-factored LSE: q = base + quad (no log); m = warp max q;
// ssum = sum exp(q-m) * D,  D = erf(x1)-erf(x2) clamped.
// ---------------------------------------------------------------------------
__global__ __launch_bounds__(256, 8) void main_kernel(const float* __restrict__ z,
                                                      const float* __restrict__ mu,
                                                      float* __restrict__ out)
{
    __shared__ float  mu_s[DIM][N_K];               // 4 KB
    __shared__ float  z_s [ROWS_PER_BLK][DIM];      // 2 KB
    __shared__ float4 c4_s[C_PAD];                  // 2560 B
    __shared__ float2 cb_s[C_PAD];                  // 1280 B
    __shared__ float  rowres[ROWS_PER_BLK];
    __shared__ float  red[256];
    __shared__ int    s_is_last;

    const int t = threadIdx.x;

    // ---- stage everything ----
    for (int i = t; i < DIM * N_K; i += 256)
        (&mu_s[0][0])[i] = mu[i];
    const int row0 = blockIdx.x * ROWS_PER_BLK;
    for (int i = t; i < ROWS_PER_BLK * DIM; i += 256)
        (&z_s[0][0])[i] = z[row0 * DIM + i];
    for (int i = t; i < C_PAD; i += 256) {
        c4_s[i] = d_c4[i];
        cb_s[i] = d_cb[i];
    }
    __syncthreads();

    const int w = t >> 5;        // warp == row within block
    const int l = t & 31;

    // 0.5*|z|^2
    float p = z_s[w][l] * z_s[w][l] + z_s[w][l + 32] * z_s[w][l + 32];
    #pragma unroll
    for (int o = 16; o; o >>= 1) p += __shfl_xor_sync(0xffffffffu, p, o);
    const float z2h = 0.5f * p;

    // g_k = dot(z_row, mu_k). Lane (k = l&15, h = l>>4) sums over dims with
    // parity h (bank-conflict-free: halves hit disjoint bank groups), fold.
    float gval;
    {
        const int k = l & 15, h = l >> 4;
        float acc = 0.f;
        #pragma unroll
        for (int i = 0; i < 32; ++i) {
            const int d = 2 * i + h;
            acc = fmaf(z_s[w][d], mu_s[d][k], acc);
        }
        acc += __shfl_xor_sync(0xffffffffu, acc, 16);
        gval = acc;              // lanes 0..15 hold g_0..g_15 (16..31 mirror)
    }

    // ---- uniform hot loop: 5 categories per lane, fully unrolled ----
    float qv[5], Dv[5];
    float m = -INFINITY;
    #pragma unroll
    for (int i = 0; i < 5; ++i) {
        const int c = l + 32 * i;
        const float4 q4 = c4_s[c];                  // k1, 0.5*mB2, recip, s2
        const float2 b2 = cb_s[c];
        const int ab = __float_as_int(b2.y);
        const float gA = __shfl_sync(0xffffffffu, gval, ab & 15);
        const float gB = __shfl_sync(0xffffffffu, gval, (ab >> 8) & 15);
        const float hbsq  = (z2h - gB) + q4.y;      // 0.5 * beta_sq
        const float delta = (q4.x - gB) + gA;
        const float nu    = delta * q4.z;
        const float qq    = fmaf(0.5f * delta, nu, -hbsq) + b2.x;
        qv[i] = qq;
        m = fmaxf(m, qq);
        const float x1 = fmaf(-nu, q4.w, q4.w);     // (1-nu)*s/sqrt2
        const float x2 = -nu * q4.w;
        Dv[i] = fmaxf(erf_fast(x1) - erf_fast(x2), 2e-16f);
    }

    // warp max of q
    #pragma unroll
    for (int o = 16; o; o >>= 1) m = fmaxf(m, __shfl_xor_sync(0xffffffffu, m, o));

    // ssum = sum exp(q - m) * D
    float ssum = 0.f;
    #pragma unroll
    for (int i = 0; i < 5; ++i) ssum = fmaf(__expf(qv[i] - m), Dv[i], ssum);

    #pragma unroll
    for (int o = 16; o; o >>= 1) ssum += __shfl_xor_sync(0xffffffffu, ssum, o);

    if (l == 0) rowres[w] = m + __logf(ssum);
    __syncthreads();

    // ---- per-block partial + last-block-done finalize ----
    if (t == 0) {
        float s = 0.f;
        #pragma unroll
        for (int r = 0; r < ROWS_PER_BLK; ++r) s += rowres[r];
        d_partials[blockIdx.x] = s;
        __threadfence();
        const unsigned int ticket = atomicAdd(&d_counter, 1u);
        s_is_last = (ticket == (unsigned)(gridDim.x - 1));
    }
    __syncthreads();

    if (s_is_last) {
        volatile float* vp = d_partials;
        float s = 0.f;
        for (int i = t; i < MAIN_BLOCKS; i += 256) s += vp[i];
        red[t] = s; __syncthreads();
        for (int o = 128; o; o >>= 1) { if (t < o) red[t] += red[t + o]; __syncthreads(); }
        if (t == 0) {
            out[0] = red[0] * (1.0f / (float)NROWS);
            d_counter = 0;                 // reset for next graph replay
        }
    }
}

// ---------------------------------------------------------------------------
extern "C" void kernel_launch(void* const* d_in, const int* in_sizes, int n_in,
                              void* d_out, int out_size)
{
    (void)in_sizes; (void)n_in; (void)out_size;
    const float* z  = (const float*)d_in[0];
    const float* pi = (const float*)d_in[1];
    const float* mu = (const float*)d_in[2];
    float* out = (float*)d_out;

    precompute_kernel<<<17, 256>>>(pi, mu);
    main_kernel<<<MAIN_BLOCKS, 256>>>(z, mu, out);
}

// round 6
// speedup vs baseline: 1.5496x; 1.1379x over previous
#include <cuda_runtime.h>
#include <math.h>

// Problem constants (fixed by the reference)
#define N_K        16
#define C_CAT      136          // 16*17/2 upper-tri pairs
#define C_PAD      160          // padded to 32*5 for a uniform unrolled loop
#define DIM        64
#define NROWS      8192         // 512 * 16
#define ROWS_PER_BLK 8
#define MAIN_BLOCKS (NROWS / ROWS_PER_BLK)   // 1024

#define LOG2PI_F   1.8378770664093453f
#define LN2_F      0.6931471805599453f
// Phi-tanh approx: Phi(x) ~= 0.5*(1+tanh(C1*x + C3*x^3)),  C1=0.79788456, C3=C1*0.044715
#define PHI_C1     0.7978845608028654f
#define PHI_C3     0.03567740813712f

// ---- device scratch (static globals; no allocation) ----
__device__ float4 d_c4[C_PAD];   // {k1, 0.5*mB2, recip, s=sqrt(clip_is)}
__device__ float2 d_cb[C_PAD];   // {base, bitcast(A | B<<8)}
__device__ float  d_partials[MAIN_BLOCKS];
__device__ unsigned int d_counter = 0;

__device__ __forceinline__ float tanh_approx(float x) {
    float r; asm("tanh.approx.f32 %0, %1;" : "=f"(r) : "f"(x)); return r;
}

// ---------------------------------------------------------------------------
// Kernel 1: per-category constants. 17 blocks x 256 thr; one WARP per category.
// Warp-local softmax. Diagonal pairs encoded as heavy categories:
//   k1=0, recip=0 -> nu=0; s=20 -> tanh(u1)=1, tanh(u2)=0 -> D=1; base=lp.
// Non-diag base = lp + 0.5*(log2pi - log(clip)) - ln2 (folds the 0.5 of the
// tanh-difference form of the cdf difference). Slots [136,160) are padding.
// ---------------------------------------------------------------------------
__global__ __launch_bounds__(256) void precompute_kernel(const float* __restrict__ pi,
                                                         const float* __restrict__ mu)
{
    const int t = threadIdx.x;
    const int w = t >> 5, l = t & 31;

    // padding slots (written by block 0's threads 136..159)
    if (blockIdx.x == 0 && t >= C_CAT && t < C_PAD) {
        d_c4[t] = make_float4(0.f, 0.f, 0.f, 20.f);
        d_cb[t] = make_float2(-1e30f, __int_as_float(0));
    }

    // warp-local softmax denominator over the 136 logits
    float v0 = pi[l], v1 = pi[l + 32], v2 = pi[l + 64], v3 = pi[l + 96];
    float v4 = (l < 8) ? pi[128 + l] : -INFINITY;
    float mx = fmaxf(fmaxf(fmaxf(v0, v1), fmaxf(v2, v3)), v4);
    #pragma unroll
    for (int o = 16; o; o >>= 1) mx = fmaxf(mx, __shfl_xor_sync(0xffffffffu, mx, o));
    float sm = __expf(v0 - mx) + __expf(v1 - mx) + __expf(v2 - mx) + __expf(v3 - mx)
             + ((l < 8) ? __expf(v4 - mx) : 0.f);
    #pragma unroll
    for (int o = 16; o; o >>= 1) sm += __shfl_xor_sync(0xffffffffu, sm, o);

    const int c = blockIdx.x * 8 + w;          // category index (< 136 always)

    // decode (A,B) from upper-tri row-major index
    int A = 0, rem = c;
    while (rem >= (N_K - A)) { rem -= (N_K - A); ++A; }
    const int B = A + rem;

    // warp-parallel 64-dim dots: lane handles dims l and l+32
    float invsig = 0.f, k1 = 0.f, mB2 = 0.f;
    #pragma unroll
    for (int h = 0; h < 2; ++h) {
        const int d = l + h * 32;
        const float mb = mu[d * N_K + B];
        const float ma = mu[d * N_K + A];
        const float a  = mb - ma;
        invsig = fmaf(a, a, invsig);
        k1     = fmaf(a, mb, k1);
        mB2    = fmaf(mb, mb, mB2);
    }
    #pragma unroll
    for (int o = 16; o; o >>= 1) {
        invsig += __shfl_xor_sync(0xffffffffu, invsig, o);
        k1     += __shfl_xor_sync(0xffffffffu, k1, o);
        mB2    += __shfl_xor_sync(0xffffffffu, mB2, o);
    }

    if (l == 0) {
        const float e  = __expf(pi[c] - mx);
        const float tp = fminf(fmaxf(e / sm, 1e-16f), 1.0f);
        const float lp = -32.0f * LOG2PI_F + logf(tp);

        float base, recip, s, k1s;
        if (A == B) {                       // diag: inv_sig == 0
            base = lp; recip = 0.f; s = 20.f; k1s = 0.f;
        } else {
            const float clip_is = fminf(fmaxf(invsig, 1e-12f), 1e30f);
            s     = sqrtf(clip_is);
            base  = lp + 0.5f * (LOG2PI_F - logf(clip_is)) - LN2_F;
            recip = 1.0f / invsig;
            k1s   = k1;
        }
        d_c4[c] = make_float4(k1s, 0.5f * mB2, recip, s);
        d_cb[c] = make_float2(base, __int_as_float(A | (B << 8)));
    }
}

// ---------------------------------------------------------------------------
// Kernel 2: main. 8 rows/block (256 thr), one warp per row.
// Exp-factored LSE: q = base + quad (no per-category log);
// D = tanh(u1) - tanh(u2)  via the Phi-tanh approximation.
// ---------------------------------------------------------------------------
__global__ __launch_bounds__(256, 8) void main_kernel(const float* __restrict__ z,
                                                      const float* __restrict__ mu,
                                                      float* __restrict__ out)
{
    __shared__ float  mu_s[DIM][N_K];               // 4 KB
    __shared__ float  z_s [ROWS_PER_BLK][DIM];      // 2 KB
    __shared__ float4 c4_s[C_PAD];                  // 2560 B
    __shared__ float2 cb_s[C_PAD];                  // 1280 B
    __shared__ float  rowres[ROWS_PER_BLK];
    __shared__ float  red[256];
    __shared__ int    s_is_last;

    const int t = threadIdx.x;

    // ---- stage everything ----
    for (int i = t; i < DIM * N_K; i += 256)
        (&mu_s[0][0])[i] = mu[i];
    const int row0 = blockIdx.x * ROWS_PER_BLK;
    for (int i = t; i < ROWS_PER_BLK * DIM; i += 256)
        (&z_s[0][0])[i] = z[row0 * DIM + i];
    for (int i = t; i < C_PAD; i += 256) {
        c4_s[i] = d_c4[i];
        cb_s[i] = d_cb[i];
    }
    __syncthreads();

    const int w = t >> 5;        // warp == row within block
    const int l = t & 31;

    // 0.5*|z|^2
    float p = z_s[w][l] * z_s[w][l] + z_s[w][l + 32] * z_s[w][l + 32];
    #pragma unroll
    for (int o = 16; o; o >>= 1) p += __shfl_xor_sync(0xffffffffu, p, o);
    const float z2h = 0.5f * p;

    // g_k = dot(z_row, mu_k). Lane (k = l&15, h = l>>4) sums over dims with
    // parity h (conflict-free), fold halves; lanes 0..15 hold g_0..g_15.
    float gval;
    {
        const int k = l & 15, h = l >> 4;
        float acc = 0.f;
        #pragma unroll
        for (int i = 0; i < 32; ++i) {
            const int d = 2 * i + h;
            acc = fmaf(z_s[w][d], mu_s[d][k], acc);
        }
        acc += __shfl_xor_sync(0xffffffffu, acc, 16);
        gval = acc;
    }

    // ---- uniform hot loop: 5 categories per lane, fully unrolled ----
    float qv[5], Dv[5];
    float m = -INFINITY;
    #pragma unroll
    for (int i = 0; i < 5; ++i) {
        const int c = l + 32 * i;
        const float4 q4 = c4_s[c];                  // k1, 0.5*mB2, recip, s
        const float2 b2 = cb_s[c];
        const int ab = __float_as_int(b2.y);
        const float gA = __shfl_sync(0xffffffffu, gval, ab & 15);
        const float gB = __shfl_sync(0xffffffffu, gval, (ab >> 8) & 15);
        const float hbsq  = (z2h - gB) + q4.y;      // 0.5 * beta_sq
        const float delta = (q4.x - gB) + gA;
        const float nu    = delta * q4.z;
        const float qq    = fmaf(0.5f * delta, nu, -hbsq) + b2.x;
        qv[i] = qq;
        m = fmaxf(m, qq);
        // eta1 = (1-nu)*s, eta2 = -nu*s ; Phi-tanh: u = eta*(C1 + C3*eta^2)
        const float ns   = nu * q4.w;
        const float eta1 = q4.w - ns;
        const float eta2 = -ns;
        const float u1 = eta1 * fmaf(PHI_C3, eta1 * eta1, PHI_C1);
        const float u2 = eta2 * fmaf(PHI_C3, eta2 * eta2, PHI_C1);
        Dv[i] = fmaxf(tanh_approx(u1) - tanh_approx(u2), 2e-16f);
    }

    // warp max of q
    #pragma unroll
    for (int o = 16; o; o >>= 1) m = fmaxf(m, __shfl_xor_sync(0xffffffffu, m, o));

    // ssum = sum exp(q - m) * D
    float ssum = 0.f;
    #pragma unroll
    for (int i = 0; i < 5; ++i) ssum = fmaf(__expf(qv[i] - m), Dv[i], ssum);

    #pragma unroll
    for (int o = 16; o; o >>= 1) ssum += __shfl_xor_sync(0xffffffffu, ssum, o);

    if (l == 0) rowres[w] = m + __logf(ssum);
    __syncthreads();

    // ---- per-block partial + last-block-done finalize ----
    if (t == 0) {
        float s = 0.f;
        #pragma unroll
        for (int r = 0; r < ROWS_PER_BLK; ++r) s += rowres[r];
        d_partials[blockIdx.x] = s;
        __threadfence();
        const unsigned int ticket = atomicAdd(&d_counter, 1u);
        s_is_last = (ticket == (unsigned)(gridDim.x - 1));
    }
    __syncthreads();

    if (s_is_last) {
        volatile float* vp = d_partials;
        float s = 0.f;
        for (int i = t; i < MAIN_BLOCKS; i += 256) s += vp[i];
        red[t] = s; __syncthreads();
        for (int o = 128; o; o >>= 1) { if (t < o) red[t] += red[t + o]; __syncthreads(); }
        if (t == 0) {
            out[0] = red[0] * (1.0f / (float)NROWS);
            d_counter = 0;                 // reset for next graph replay
        }
    }
}

// ---------------------------------------------------------------------------
extern "C" void kernel_launch(void* const* d_in, const int* in_sizes, int n_in,
                              void* d_out, int out_size)
{
    (void)in_sizes; (void)n_in; (void)out_size;
    const float* z  = (const float*)d_in[0];
    const float* pi = (const float*)d_in[1];
    const float* mu = (const float*)d_in[2];
    float* out = (float*)d_out;

    precompute_kernel<<<17, 256>>>(pi, mu);
    main_kernel<<<MAIN_BLOCKS, 256>>>(z, mu, out);
}